// round 16
// baseline (speedup 1.0000x reference)
#include <cuda_runtime.h>
#include <cstdint>

// out[n,m,q] = sum_d x[n,m,d] * W[sidx[n],d,q]
// x: [16384,64,128] f32, sidx: [16384] i32/i64, W: [8,128,128] f32
// Route: species-grouped persistent CTAs + single-term fp16 mma.sync
// (R14: 192.5 us, rel_err 2.94e-4, ~93% of LTS bandwidth cap).
// R16: W fp32->fp16 transpose folded into mma_main prologue (prep_wimg
// launch removed); g_cnt re-zeroed at end of mma_main by slot-0 blocks.

#define NSAMP  16384
#define NCOMP  64
#define DIN    128
#define DOUT   128
#define NSPEC  8
#define SLOTS  38                  // 2 CTAs/SM * 19
#define GRIDSZ (NSPEC * SLOTS)     // 304 = 2 * 152 SMs

#define KPAD   136                 // padded k-stride (bank-rotation 4i mod 32)
#define WELEMS (DOUT * KPAD)       // 17408 fp16 per W image
#define CONVB  (NCOMP * KPAD * 2)  // 17408 B: one x fp16 image

// ---------------- device scratch ----------------
__device__ int g_cnt[NSPEC];                    // zero-init; re-zeroed per call
__device__ int g_bucket[NSPEC][NSAMP];          // fixed-cap buckets

// ---------------- smem layout (bytes) ----------------
#define SM_W     0
#define SM_CONV0 (SM_W + WELEMS * 2)          // 34816
#define SM_CONV1 (SM_CONV0 + CONVB)           // 52224 (also W-transpose scratch)
#define SM_TOTAL (SM_CONV1 + CONVB)           // 69632

// ---------------- PTX helpers ----------------
__device__ __forceinline__ uint32_t smem_u32(const void* p) {
    uint32_t a;
    asm("{ .reg .u64 t; cvta.to.shared.u64 t, %1; cvt.u32.u64 %0, t; }"
        : "=r"(a) : "l"(p));
    return a;
}
__device__ __forceinline__ void ldsm4(uint32_t* r, uint32_t addr) {
    asm volatile("ldmatrix.sync.aligned.m8n8.x4.shared.b16 {%0,%1,%2,%3}, [%4];"
                 : "=r"(r[0]), "=r"(r[1]), "=r"(r[2]), "=r"(r[3]) : "r"(addr));
}
__device__ __forceinline__ void mma_f16(float* d, const uint32_t* a,
                                        const uint32_t* b) {
    asm volatile(
        "mma.sync.aligned.m16n8k16.row.col.f32.f16.f16.f32 "
        "{%0,%1,%2,%3}, {%4,%5,%6,%7}, {%8,%9}, {%0,%1,%2,%3};"
        : "+f"(d[0]), "+f"(d[1]), "+f"(d[2]), "+f"(d[3])
        : "r"(a[0]), "r"(a[1]), "r"(a[2]), "r"(a[3]), "r"(b[0]), "r"(b[1]));
}
__device__ __forceinline__ uint32_t pack_f16x2(float fh, float fl) {
    uint32_t r;
    asm("cvt.rn.f16x2.f32 %0, %1, %2;" : "=r"(r) : "f"(fh), "f"(fl));
    return r;
}
__device__ __forceinline__ float4 ldg_cs4(const float4* p) {
    float4 v;
    asm volatile("ld.global.cs.v4.f32 {%0,%1,%2,%3}, [%4];"
                 : "=f"(v.x), "=f"(v.y), "=f"(v.z), "=f"(v.w) : "l"(p));
    return v;
}

// ---------------- prep: detect + decode + bucket scatter (64 blocks) ----
__global__ __launch_bounds__(256, 2)
void prep_dcs(const unsigned int* __restrict__ raw)
{
    const int tid  = threadIdx.x;
    const int lane = tid & 31;
    const int b    = blockIdx.x;

    // local int64 detection: 128 odd words, always within first 16384 words
    int bad = 0;
    if (tid < 128) {
        const int w = 2 * (b * 128 + tid) + 1;   // max 16383
        if (raw[w] != 0u) bad = 1;
    }
    const bool is64 = !__syncthreads_or(bad);

    const int n = b * 256 + tid;
    unsigned u = is64 ? raw[2 * n] : raw[n];
    if (u > 7u) u = 7u;
    const int s = (int)u;

    #pragma unroll
    for (int sp = 0; sp < NSPEC; sp++) {
        unsigned m = __ballot_sync(0xFFFFFFFFu, s == sp);
        if (s == sp) {
            int rank = __popc(m & ((1u << lane) - 1u));
            int base = 0;
            if (rank == 0) base = atomicAdd(&g_cnt[sp], __popc(m));
            base = __shfl_sync(m, base, __ffs(m) - 1);
            g_bucket[sp][base + rank] = n;
        }
    }
}

// ---------------- main kernel ----------------
__global__ __launch_bounds__(256, 2)
void mma_main(const float* __restrict__ x, const float* __restrict__ W,
              float* __restrict__ out)
{
    extern __shared__ char smem[];
    const uint32_t sb = smem_u32(smem);
    const int tid  = threadIdx.x;
    const int lane = tid & 31;
    const int wid  = tid >> 5;
    const int wm   = wid >> 2;           // 0..1  (m tile 32)
    const int wn   = wid & 3;            // 0..3  (n tile 32)
    const int spec = blockIdx.x / SLOTS;
    const int slot = blockIdx.x % SLOTS;

    const int cnt = g_cnt[spec];
    const int* lst = g_bucket[spec];
    if (slot >= cnt) return;

    // ---- issue sample-0 LDGs first (latency hides under W conversion) ----
    int n_cur = lst[slot];
    float4 xr[8];
    {
        const float4* xg = (const float4*)(x + (size_t)n_cur * (NCOMP * DIN));
        #pragma unroll
        for (int i = 0; i < 8; i++) xr[i] = ldg_cs4(xg + tid + i * 256);
    }

    // ---- W fp32 -> fp16 transposed image in SM_W (scratch in CONV1) ----
    {
        float* tile = (float*)(smem + SM_CONV1);     // 32x33 floats = 4224 B
        const float* Ws = W + (size_t)spec * (DIN * DOUT);
        const int c = tid & 31;
        const int r = tid >> 5;                      // 0..7
        #pragma unroll
        for (int tk = 0; tk < 4; tk++) {
            const int k0 = tk * 32;
            #pragma unroll
            for (int tq = 0; tq < 4; tq++) {
                const int q0 = tq * 32;
                __syncthreads();
                #pragma unroll
                for (int rr = r; rr < 32; rr += 8)   // coalesced read: vary q
                    tile[rr * 33 + c] = Ws[(k0 + rr) * DOUT + (q0 + c)];
                __syncthreads();
                #pragma unroll
                for (int rr = r; rr < 32; rr += 8) { // write: vary k
                    float v = tile[c * 33 + rr];     // W[k0+c][q0+rr]
                    *(uint16_t*)(smem + SM_W +
                        ((q0 + rr) * KPAD + (k0 + c)) * 2) =
                        (uint16_t)(pack_f16x2(v, 0.0f) >> 16);
                }
            }
        }
    }

    // ldmatrix lane address components
    const int a_row  = (lane & 15);
    const int a_koff = (lane >> 4) * 8;
    const int b_row  = ((lane >> 4) * 8) + (lane & 7);
    const int b_koff = ((lane >> 3) & 1) * 8;

    uint32_t aOff[2];
    #pragma unroll
    for (int mi = 0; mi < 2; mi++)
        aOff[mi] = ((wm * 32 + mi * 16 + a_row) * KPAD + a_koff) * 2;
    uint32_t bAddr[2];
    #pragma unroll
    for (int p = 0; p < 2; p++)
        bAddr[p] = sb + SM_W +
            ((wn * 32 + p * 16 + b_row) * KPAD + b_koff) * 2;

    uint32_t cOff[8];
    #pragma unroll
    for (int i = 0; i < 8; i++) {
        const int idx = tid + i * 256;
        cOff[i] = (uint32_t)(((idx >> 5) * KPAD + (idx & 31) * 4) * 2);
    }

    // ---- convert sample 0 regs -> CONV0 ----
    #pragma unroll
    for (int i = 0; i < 8; i++) {
        uint32_t h01 = pack_f16x2(xr[i].y, xr[i].x);
        uint32_t h23 = pack_f16x2(xr[i].w, xr[i].z);
        *(uint2*)(smem + SM_CONV0 + cOff[i]) = make_uint2(h01, h23);
    }
    __syncthreads();                     // W image + CONV0 visible

    for (int j = slot, t = 0; j < cnt; j += SLOTS, t++) {
        // ---- prefetch sample t+1 into regs (skipped on last iteration) ----
        const int jn = j + SLOTS;
        const bool has_next = (jn < cnt);
        const int n_next = has_next ? lst[jn] : n_cur;
        if (has_next) {
            const float4* xg =
                (const float4*)(x + (size_t)n_next * (NCOMP * DIN));
            #pragma unroll
            for (int i = 0; i < 8; i++) xr[i] = ldg_cs4(xg + tid + i * 256);
        }

        // ---- single-term fp16 mma on conv[t&1] ----
        const uint32_t xb = sb + ((t & 1) ? SM_CONV1 : SM_CONV0);
        float acc[2][4][4];
        #pragma unroll
        for (int mi = 0; mi < 2; mi++)
            #pragma unroll
            for (int ni = 0; ni < 4; ni++)
                #pragma unroll
                for (int e = 0; e < 4; e++) acc[mi][ni][e] = 0.0f;

        #pragma unroll
        for (int ks = 0; ks < 8; ks++) {
            const uint32_t kb = ks * 32;
            uint32_t A[2][4], B[2][4];
            #pragma unroll
            for (int mi = 0; mi < 2; mi++)
                ldsm4(A[mi], xb + aOff[mi] + kb);
            #pragma unroll
            for (int p = 0; p < 2; p++)
                ldsm4(B[p], bAddr[p] + kb);
            #pragma unroll
            for (int mi = 0; mi < 2; mi++)
                #pragma unroll
                for (int p = 0; p < 2; p++)
                    #pragma unroll
                    for (int h = 0; h < 2; h++)
                        mma_f16(acc[mi][p * 2 + h], A[mi], &B[p][2 * h]);
        }

        // ---- epilogue: direct STG.64 for sample t ----
        {
            const int r  = lane >> 2;
            const int c2 = 2 * (lane & 3);
            float* ob = out + (size_t)n_cur * (NCOMP * DOUT);
            #pragma unroll
            for (int mi = 0; mi < 2; mi++) {
                const int gm = wm * 32 + mi * 16 + r;
                #pragma unroll
                for (int ni = 0; ni < 4; ni++) {
                    const int gq = wn * 32 + ni * 8 + c2;
                    float* o = ob + gm * DOUT + gq;
                    *(float2*)o = make_float2(acc[mi][ni][0], acc[mi][ni][1]);
                    *(float2*)(o + 8 * DOUT) =
                        make_float2(acc[mi][ni][2], acc[mi][ni][3]);
                }
            }
        }

        // ---- convert regs(t+1) -> conv[(t+1)&1] ----
        if (has_next) {
            char* cbuf = smem + (((t + 1) & 1) ? SM_CONV1 : SM_CONV0);
            #pragma unroll
            for (int i = 0; i < 8; i++) {
                uint32_t h01 = pack_f16x2(xr[i].y, xr[i].x);
                uint32_t h23 = pack_f16x2(xr[i].w, xr[i].z);
                *(uint2*)(cbuf + cOff[i]) = make_uint2(h01, h23);
            }
        }

        __syncthreads();   // conv(t+1) visible; conv[t&1] free next iter
        n_cur = n_next;
    }

    // ---- re-zero g_cnt for the next call (slot-0 block per species).
    // Safe: grid = 2 CTAs/SM * 152 SMs = fully resident, so every block has
    // read g_cnt long before any block reaches this point.
    if (slot == 0 && tid == 0) g_cnt[spec] = 0;
}

// ---------------- launch ----------------
extern "C" void kernel_launch(void* const* d_in, const int* in_sizes, int n_in,
                              void* d_out, int out_size)
{
    const float*        x    = nullptr;
    const unsigned int* sidx = nullptr;
    const float*        W    = nullptr;
    for (int i = 0; i < n_in; i++) {
        if      (in_sizes[i] == NSAMP * NCOMP * DIN) x    = (const float*)d_in[i];
        else if (in_sizes[i] == NSAMP)               sidx = (const unsigned int*)d_in[i];
        else if (in_sizes[i] == NSPEC * DIN * DOUT)  W    = (const float*)d_in[i];
    }
    float* out = (float*)d_out;

    prep_dcs<<<NSAMP / 256, 256>>>(sidx);

    cudaFuncSetAttribute(mma_main, cudaFuncAttributeMaxDynamicSharedMemorySize,
                         SM_TOTAL);
    mma_main<<<GRIDSZ, 256, SM_TOTAL>>>(x, W, out);
}

// round 17
// speedup vs baseline: 1.0789x; 1.0789x over previous
#include <cuda_runtime.h>
#include <cstdint>

// out[n,m,q] = sum_d x[n,m,d] * W[sidx[n],d,q]
// x: [16384,64,128] f32, sidx: [16384] i32/i64, W: [8,128,128] f32
// Route: species-grouped persistent CTAs + single-term fp16 mma.sync
// (R14 core: 192.5 us, rel_err 2.94e-4). R17: prep_wimg + prep_dcs fused
// into ONE concurrent launch (96 blocks); g_cnt re-zeroed at end of
// mma_main (single-wave grid makes this safe, validated in R16).

#define NSAMP  16384
#define NCOMP  64
#define DIN    128
#define DOUT   128
#define NSPEC  8
#define SLOTS  38                  // 2 CTAs/SM * 19
#define GRIDSZ (NSPEC * SLOTS)     // 304 = 2 * 152 SMs

#define KPAD   136                 // padded k-stride (bank-rotation 4i mod 32)
#define WELEMS (DOUT * KPAD)       // 17408 fp16 per W image
#define CONVB  (NCOMP * KPAD * 2)  // 17408 B: one x fp16 image

// ---------------- device scratch ----------------
__device__ int g_cnt[NSPEC];                    // zero-init; re-zeroed by mma_main
__device__ int g_bucket[NSPEC][NSAMP];          // fixed-cap buckets
__device__ __align__(16) uint16_t g_wh[NSPEC][WELEMS];   // Wt[q][k] fp16 RN

// ---------------- smem layout (bytes) ----------------
#define SM_W     0
#define SM_CONV0 (SM_W + WELEMS * 2)          // 34816
#define SM_CONV1 (SM_CONV0 + CONVB)           // 52224
#define SM_TOTAL (SM_CONV1 + CONVB)           // 69632

// ---------------- PTX helpers ----------------
__device__ __forceinline__ uint32_t smem_u32(const void* p) {
    uint32_t a;
    asm("{ .reg .u64 t; cvta.to.shared.u64 t, %1; cvt.u32.u64 %0, t; }"
        : "=r"(a) : "l"(p));
    return a;
}
__device__ __forceinline__ void cp16(uint32_t dst, const void* src) {
    asm volatile("cp.async.cg.shared.global [%0], [%1], 16;"
                 :: "r"(dst), "l"(src) : "memory");
}
__device__ __forceinline__ void cp_commit() {
    asm volatile("cp.async.commit_group;" ::: "memory");
}
__device__ __forceinline__ void cp_wait0() {
    asm volatile("cp.async.wait_group 0;" ::: "memory");
}
__device__ __forceinline__ void ldsm4(uint32_t* r, uint32_t addr) {
    asm volatile("ldmatrix.sync.aligned.m8n8.x4.shared.b16 {%0,%1,%2,%3}, [%4];"
                 : "=r"(r[0]), "=r"(r[1]), "=r"(r[2]), "=r"(r[3]) : "r"(addr));
}
__device__ __forceinline__ void mma_f16(float* d, const uint32_t* a,
                                        const uint32_t* b) {
    asm volatile(
        "mma.sync.aligned.m16n8k16.row.col.f32.f16.f16.f32 "
        "{%0,%1,%2,%3}, {%4,%5,%6,%7}, {%8,%9}, {%0,%1,%2,%3};"
        : "+f"(d[0]), "+f"(d[1]), "+f"(d[2]), "+f"(d[3])
        : "r"(a[0]), "r"(a[1]), "r"(a[2]), "r"(a[3]), "r"(b[0]), "r"(b[1]));
}
__device__ __forceinline__ uint32_t pack_f16x2(float fh, float fl) {
    uint32_t r;
    asm("cvt.rn.f16x2.f32 %0, %1, %2;" : "=r"(r) : "f"(fh), "f"(fl));
    return r;
}

// ---------------- fused prep: 96 blocks, one launch ----------------
// Blocks 0..31  : W transpose -> fp16 image (s = b>>2, k-tile = b&3)
// Blocks 32..95 : sidx detect + decode + bucket scatter
__global__ __launch_bounds__(256, 4)
void prep_fused(const float* __restrict__ W,
                const unsigned int* __restrict__ raw)
{
    const int tid = threadIdx.x;

    if (blockIdx.x < 32) {
        // ---- W transpose (tiled, coalesced) ----
        __shared__ float tile[32][33];
        const int s  = blockIdx.x >> 2;
        const int tk = blockIdx.x & 3;
        const int c = tid & 31;
        const int r = tid >> 5;          // 0..7
        const int k0 = tk * 32;

        for (int tq = 0; tq < 4; tq++) {
            const int q0 = tq * 32;
            __syncthreads();
            #pragma unroll
            for (int rr = r; rr < 32; rr += 8)       // coalesced read: vary q
                tile[rr][c] = W[s * DIN * DOUT + (k0 + rr) * DOUT + (q0 + c)];
            __syncthreads();
            #pragma unroll
            for (int rr = r; rr < 32; rr += 8) {     // coalesced write: vary k
                float v = tile[c][rr];
                g_wh[s][(q0 + rr) * KPAD + (k0 + c)] =
                    (uint16_t)(pack_f16x2(v, 0.0f) >> 16);
            }
        }
    } else {
        // ---- sidx detect + decode + bucket scatter ----
        const int b    = blockIdx.x - 32;            // 0..63
        const int lane = tid & 31;

        // local int64 detection: 128 odd words, within first 16384 words
        int bad = 0;
        if (tid < 128) {
            const int w = 2 * (b * 128 + tid) + 1;   // max 16383
            if (raw[w] != 0u) bad = 1;
        }
        const bool is64 = !__syncthreads_or(bad);

        const int n = b * 256 + tid;
        unsigned u = is64 ? raw[2 * n] : raw[n];
        if (u > 7u) u = 7u;
        const int s = (int)u;

        #pragma unroll
        for (int sp = 0; sp < NSPEC; sp++) {
            unsigned m = __ballot_sync(0xFFFFFFFFu, s == sp);
            if (s == sp) {
                int rank = __popc(m & ((1u << lane) - 1u));
                int base = 0;
                if (rank == 0) base = atomicAdd(&g_cnt[sp], __popc(m));
                base = __shfl_sync(m, base, __ffs(m) - 1);
                g_bucket[sp][base + rank] = n;
            }
        }
    }
}

// ---------------- main kernel (R14-proven core) ----------------
__global__ __launch_bounds__(256, 2)
void mma_main(const float* __restrict__ x, float* __restrict__ out)
{
    extern __shared__ char smem[];
    const uint32_t sb = smem_u32(smem);
    const int tid  = threadIdx.x;
    const int lane = tid & 31;
    const int wid  = tid >> 5;
    const int wm   = wid >> 2;           // 0..1  (m tile 32)
    const int wn   = wid & 3;            // 0..3  (n tile 32)
    const int spec = blockIdx.x / SLOTS;
    const int slot = blockIdx.x % SLOTS;

    // ---- stage W image (fp16, 34 KB) once via cp.async ----
    {
        const uint16_t* wh = g_wh[spec];
        #pragma unroll
        for (int i = 0; i < 9; i++) {
            int idx = tid + i * 256;
            if (idx < WELEMS / 8)
                cp16(sb + SM_W + idx * 16, wh + idx * 8);
        }
        cp_commit();
    }

    const int cnt = g_cnt[spec];
    const int* lst = g_bucket[spec];
    if (slot >= cnt) { cp_wait0(); return; }

    // ldmatrix lane address components
    const int a_row  = (lane & 15);
    const int a_koff = (lane >> 4) * 8;
    const int b_row  = ((lane >> 4) * 8) + (lane & 7);
    const int b_koff = ((lane >> 3) & 1) * 8;

    uint32_t aOff[2];
    #pragma unroll
    for (int mi = 0; mi < 2; mi++)
        aOff[mi] = ((wm * 32 + mi * 16 + a_row) * KPAD + a_koff) * 2;
    uint32_t bAddr[2];
    #pragma unroll
    for (int p = 0; p < 2; p++)
        bAddr[p] = sb + SM_W +
            ((wn * 32 + p * 16 + b_row) * KPAD + b_koff) * 2;

    uint32_t cOff[8];
    #pragma unroll
    for (int i = 0; i < 8; i++) {
        const int idx = tid + i * 256;
        cOff[i] = (uint32_t)(((idx >> 5) * KPAD + (idx & 31) * 4) * 2);
    }

    // ---- prologue: LDG sample 0, convert into CONV0 ----
    int n_cur = lst[slot];
    float4 xr[8];
    {
        const float4* xg = (const float4*)(x + (size_t)n_cur * (NCOMP * DIN));
        #pragma unroll
        for (int i = 0; i < 8; i++) xr[i] = xg[tid + i * 256];
    }
    cp_wait0();                          // W resident
    #pragma unroll
    for (int i = 0; i < 8; i++) {
        uint32_t h01 = pack_f16x2(xr[i].y, xr[i].x);
        uint32_t h23 = pack_f16x2(xr[i].w, xr[i].z);
        *(uint2*)(smem + SM_CONV0 + cOff[i]) = make_uint2(h01, h23);
    }
    __syncthreads();

    for (int j = slot, t = 0; j < cnt; j += SLOTS, t++) {
        // ---- prefetch sample t+1 into regs (skipped on last iteration) ----
        const int jn = j + SLOTS;
        const bool has_next = (jn < cnt);
        const int n_next = has_next ? lst[jn] : n_cur;
        if (has_next) {
            const float4* xg =
                (const float4*)(x + (size_t)n_next * (NCOMP * DIN));
            #pragma unroll
            for (int i = 0; i < 8; i++) xr[i] = xg[tid + i * 256];
        }

        // ---- single-term fp16 mma on conv[t&1] ----
        const uint32_t xb = sb + ((t & 1) ? SM_CONV1 : SM_CONV0);
        float acc[2][4][4];
        #pragma unroll
        for (int mi = 0; mi < 2; mi++)
            #pragma unroll
            for (int ni = 0; ni < 4; ni++)
                #pragma unroll
                for (int e = 0; e < 4; e++) acc[mi][ni][e] = 0.0f;

        #pragma unroll
        for (int ks = 0; ks < 8; ks++) {
            const uint32_t kb = ks * 32;
            uint32_t A[2][4], B[2][4];
            #pragma unroll
            for (int mi = 0; mi < 2; mi++)
                ldsm4(A[mi], xb + aOff[mi] + kb);
            #pragma unroll
            for (int p = 0; p < 2; p++)
                ldsm4(B[p], bAddr[p] + kb);
            #pragma unroll
            for (int mi = 0; mi < 2; mi++)
                #pragma unroll
                for (int p = 0; p < 2; p++)
                    #pragma unroll
                    for (int h = 0; h < 2; h++)
                        mma_f16(acc[mi][p * 2 + h], A[mi], &B[p][2 * h]);
        }

        // ---- epilogue: direct STG.64 for sample t ----
        {
            const int r  = lane >> 2;
            const int c2 = 2 * (lane & 3);
            float* ob = out + (size_t)n_cur * (NCOMP * DOUT);
            #pragma unroll
            for (int mi = 0; mi < 2; mi++) {
                const int gm = wm * 32 + mi * 16 + r;
                #pragma unroll
                for (int ni = 0; ni < 4; ni++) {
                    const int gq = wn * 32 + ni * 8 + c2;
                    float* o = ob + gm * DOUT + gq;
                    *(float2*)o = make_float2(acc[mi][ni][0], acc[mi][ni][1]);
                    *(float2*)(o + 8 * DOUT) =
                        make_float2(acc[mi][ni][2], acc[mi][ni][3]);
                }
            }
        }

        // ---- convert regs(t+1) -> conv[(t+1)&1] ----
        if (has_next) {
            char* cbuf = smem + (((t + 1) & 1) ? SM_CONV1 : SM_CONV0);
            #pragma unroll
            for (int i = 0; i < 8; i++) {
                uint32_t h01 = pack_f16x2(xr[i].y, xr[i].x);
                uint32_t h23 = pack_f16x2(xr[i].w, xr[i].z);
                *(uint2*)(cbuf + cOff[i]) = make_uint2(h01, h23);
            }
        }

        __syncthreads();   // conv(t+1) visible; conv[t&1] free next iter
        n_cur = n_next;
    }

    // ---- re-zero g_cnt for the next call (slot-0 block per species).
    // Safe: grid = 2 CTAs/SM * 152 SMs = single full wave; every block reads
    // g_cnt in its prologue long before any block reaches this point.
    if (slot == 0 && tid == 0) g_cnt[spec] = 0;
}

// ---------------- launch ----------------
extern "C" void kernel_launch(void* const* d_in, const int* in_sizes, int n_in,
                              void* d_out, int out_size)
{
    const float*        x    = nullptr;
    const unsigned int* sidx = nullptr;
    const float*        W    = nullptr;
    for (int i = 0; i < n_in; i++) {
        if      (in_sizes[i] == NSAMP * NCOMP * DIN) x    = (const float*)d_in[i];
        else if (in_sizes[i] == NSAMP)               sidx = (const unsigned int*)d_in[i];
        else if (in_sizes[i] == NSPEC * DIN * DOUT)  W    = (const float*)d_in[i];
    }
    float* out = (float*)d_out;

    prep_fused<<<96, 256>>>(W, sidx);

    cudaFuncSetAttribute(mma_main, cudaFuncAttributeMaxDynamicSharedMemorySize,
                         SM_TOTAL);
    mma_main<<<GRIDSZ, 256, SM_TOTAL>>>(x, out);
}